// round 9
// baseline (speedup 1.0000x reference)
#include <cuda_runtime.h>
#include <cuda_bf16.h>
#include <math.h>
#include <stdint.h>

// Problem dims (fixed by the dataset)
#define B_  64
#define S_  1024
#define I_  1024
#define H_  1024

// =================== base-ISA PTX helpers (no sm_103a-only features) ===========
__device__ __forceinline__ uint32_t smem_u32(const void* p) {
    uint32_t a;
    asm("{ .reg .u64 t; cvta.to.shared.u64 t, %1; cvt.u32.u64 %0, t; }"
        : "=r"(a) : "l"(p));
    return a;
}
__device__ __forceinline__ void cp_async16(uint32_t saddr, const void* gaddr) {
    asm volatile("cp.async.cg.shared.global [%0], [%1], 16;"
                 :: "r"(saddr), "l"(gaddr));
}
__device__ __forceinline__ void cp_commit() {
    asm volatile("cp.async.commit_group;" ::: "memory");
}
template <int N>
__device__ __forceinline__ void cp_wait() {
    asm volatile("cp.async.wait_group %0;" :: "n"(N) : "memory");
}
__device__ __forceinline__ void ldsm4(uint32_t* r, uint32_t a) {
    asm volatile("ldmatrix.sync.aligned.m8n8.x4.shared.b16 {%0,%1,%2,%3}, [%4];"
                 : "=r"(r[0]), "=r"(r[1]), "=r"(r[2]), "=r"(r[3]) : "r"(a));
}
__device__ __forceinline__ void ldsm2(uint32_t* r, uint32_t a) {
    asm volatile("ldmatrix.sync.aligned.m8n8.x2.shared.b16 {%0,%1}, [%2];"
                 : "=r"(r[0]), "=r"(r[1]) : "r"(a));
}
// D(f32) += A(bf16) * B(bf16)^T, m16n8k16
__device__ __forceinline__ void mma16816(float* c, const uint32_t* a, const uint32_t* b) {
    asm volatile(
        "mma.sync.aligned.m16n8k16.row.col.f32.bf16.bf16.f32 "
        "{%0,%1,%2,%3}, {%4,%5,%6,%7}, {%8,%9}, {%0,%1,%2,%3};"
        : "+f"(c[0]), "+f"(c[1]), "+f"(c[2]), "+f"(c[3])
        : "r"(a[0]), "r"(a[1]), "r"(a[2]), "r"(a[3]), "r"(b[0]), "r"(b[1]));
}

// =================== persistent state (no allocations allowed) ===================
__device__ unsigned g_bar;             // grid barrier arrival counter
// hidden state ping-pong, bf16 hi/lo split, TILED layout:
//   elem (b,k) at (k>>4)*1024 + b*16 + (k&15)   (i.e. [k/16][b][16])
__device__ __nv_bfloat16 g_hb[2][2][B_ * H_];
// bf16-split scratch for phase-1 tensor-core GEMM
__device__ __nv_bfloat16 g_xhi[(size_t)B_ * S_ * I_];
__device__ __nv_bfloat16 g_xlo[(size_t)B_ * S_ * I_];
__device__ __nv_bfloat16 g_whi[(size_t)H_ * I_];
__device__ __nv_bfloat16 g_wlo[(size_t)H_ * I_];

// =================== init: convert h0 -> tiled bf16 hi/lo, reset barrier =========
__global__ void init_kernel(const float* __restrict__ h0) {
    int i = blockIdx.x * blockDim.x + threadIdx.x;
    if (i < B_ * H_) {
        int b = i >> 10, k = i & 1023;
        float v = h0[i];
        __nv_bfloat16 h = __float2bfloat16(v);
        __nv_bfloat16 l = __float2bfloat16(v - __bfloat162float(h));
        int idx = (k >> 4) * 1024 + b * 16 + (k & 15);
        g_hb[0][0][idx] = h;
        g_hb[0][1][idx] = l;
    }
    if (i == 0) g_bar = 0u;
}

// =================== fp32 -> (hi, lo) bf16 split (x, Wih) ===================
__global__ void convert_x_kernel(const float* __restrict__ src) {
    size_t i = (size_t)blockIdx.x * blockDim.x + threadIdx.x;   // one float4
    float4 v = ((const float4*)src)[i];
    __nv_bfloat16 hx = __float2bfloat16(v.x), hy = __float2bfloat16(v.y);
    __nv_bfloat16 hz = __float2bfloat16(v.z), hw = __float2bfloat16(v.w);
    __nv_bfloat16 lx = __float2bfloat16(v.x - __bfloat162float(hx));
    __nv_bfloat16 ly = __float2bfloat16(v.y - __bfloat162float(hy));
    __nv_bfloat16 lz = __float2bfloat16(v.z - __bfloat162float(hz));
    __nv_bfloat16 lw = __float2bfloat16(v.w - __bfloat162float(hw));
    __nv_bfloat162* dh = ((__nv_bfloat162*)g_xhi) + 2 * i;
    __nv_bfloat162* dl = ((__nv_bfloat162*)g_xlo) + 2 * i;
    dh[0] = __halves2bfloat162(hx, hy); dh[1] = __halves2bfloat162(hz, hw);
    dl[0] = __halves2bfloat162(lx, ly); dl[1] = __halves2bfloat162(lz, lw);
}
__global__ void convert_w_kernel(const float* __restrict__ src) {
    size_t i = (size_t)blockIdx.x * blockDim.x + threadIdx.x;
    float4 v = ((const float4*)src)[i];
    __nv_bfloat16 hx = __float2bfloat16(v.x), hy = __float2bfloat16(v.y);
    __nv_bfloat16 hz = __float2bfloat16(v.z), hw = __float2bfloat16(v.w);
    __nv_bfloat16 lx = __float2bfloat16(v.x - __bfloat162float(hx));
    __nv_bfloat16 ly = __float2bfloat16(v.y - __bfloat162float(hy));
    __nv_bfloat16 lz = __float2bfloat16(v.z - __bfloat162float(hz));
    __nv_bfloat16 lw = __float2bfloat16(v.w - __bfloat162float(hw));
    __nv_bfloat162* dh = ((__nv_bfloat162*)g_whi) + 2 * i;
    __nv_bfloat162* dl = ((__nv_bfloat162*)g_wlo) + 2 * i;
    dh[0] = __halves2bfloat162(hx, hy); dh[1] = __halves2bfloat162(hz, hw);
    dl[0] = __halves2bfloat162(lx, ly); dl[1] = __halves2bfloat162(lz, lw);
}

// =================== Phase 1: mma.sync bf16-split GEMM (proven R8) ==============
#define BKE   16
#define LDT   24
#define TILE_E (128 * LDT)          // 3072 elems = 6144 B
#define NKC   (I_ / BKE)            // 64

__global__ __launch_bounds__(256) void gemm_wx_mma(const float* __restrict__ bias,
                                                   float* __restrict__ C) {
    __shared__ __nv_bfloat16 stg[2][4][TILE_E];   // 49152 B

    const int tid = threadIdx.x;
    const int wid = tid >> 5, lid = tid & 31;
    const int wm = wid >> 2, wn = wid & 3;        // 2 x 4 warps
    const int m0 = blockIdx.y * 128, n0 = blockIdx.x * 128;
    const uint32_t sb = smem_u32(stg);

    const int ltile = tid >> 6;                   // 0..3
    const int lrow2 = (tid & 63) * 2;

    const int grp = lid >> 3, li8 = lid & 7;
    uint32_t offA[4], offB[4];
    #pragma unroll
    for (int f = 0; f < 4; f++)
        offA[f] = (uint32_t)((wm * 64 + f * 16 + li8 + (grp & 1) * 8) * 48 + (grp >> 1) * 16);
    #pragma unroll
    for (int nf = 0; nf < 4; nf++)
        offB[nf] = (uint32_t)((wn * 32 + nf * 8 + li8) * 48 + (grp & 1) * 16);

    float acc[4][4][4];
    #pragma unroll
    for (int f = 0; f < 4; f++)
        #pragma unroll
        for (int nf = 0; nf < 4; nf++)
            #pragma unroll
            for (int q = 0; q < 4; q++) acc[f][nf][q] = 0.f;

    auto load_stage = [&](int kc, int s) {
        const int koff = kc * BKE;
        #pragma unroll
        for (int i = 0; i < 4; i++) {
            const int row = lrow2 + (i >> 1), seg = i & 1;
            const __nv_bfloat16* gp;
            if      (ltile == 0) gp = g_xhi + (size_t)(m0 + row) * I_ + koff + seg * 8;
            else if (ltile == 1) gp = g_xlo + (size_t)(m0 + row) * I_ + koff + seg * 8;
            else if (ltile == 2) gp = g_whi + (size_t)(n0 + row) * I_ + koff + seg * 8;
            else                 gp = g_wlo + (size_t)(n0 + row) * I_ + koff + seg * 8;
            uint32_t sa = sb + (uint32_t)(((s * 4 + ltile) * TILE_E + row * LDT + seg * 8) * 2);
            cp_async16(sa, gp);
        }
        cp_commit();
    };

    load_stage(0, 0);

    for (int kc = 0; kc < NKC; kc++) {
        const int s = kc & 1;
        if (kc + 1 < NKC) { load_stage(kc + 1, s ^ 1); cp_wait<1>(); }
        else             { cp_wait<0>(); }
        __syncthreads();

        const uint32_t base = sb + (uint32_t)(s * 4 * TILE_E * 2);
        const uint32_t tAh = base, tAl = base + 6144, tBh = base + 12288, tBl = base + 18432;

        uint32_t Ah[4][4], Al[4][4], Bh[4][2], Bl[4][2];
        #pragma unroll
        for (int f = 0; f < 4; f++) { ldsm4(Ah[f], tAh + offA[f]); ldsm4(Al[f], tAl + offA[f]); }
        #pragma unroll
        for (int nf = 0; nf < 4; nf++) { ldsm2(Bh[nf], tBh + offB[nf]); ldsm2(Bl[nf], tBl + offB[nf]); }

        #pragma unroll
        for (int f = 0; f < 4; f++)
            #pragma unroll
            for (int nf = 0; nf < 4; nf++) {
                mma16816(acc[f][nf], Ah[f], Bh[nf]);
                mma16816(acc[f][nf], Ah[f], Bl[nf]);
                mma16816(acc[f][nf], Al[f], Bh[nf]);
            }
        __syncthreads();
    }

    #pragma unroll
    for (int nf = 0; nf < 4; nf++) {
        const int col = n0 + wn * 32 + nf * 8 + (lid & 3) * 2;
        const float bx = bias[col], by = bias[col + 1];
        #pragma unroll
        for (int f = 0; f < 4; f++) {
            const size_t r0 = (size_t)(m0 + wm * 64 + f * 16 + (lid >> 2));
            float* cp = C + r0 * H_ + col;
            float2 v0 = make_float2(acc[f][nf][0] + bx, acc[f][nf][1] + by);
            float2 v1 = make_float2(acc[f][nf][2] + bx, acc[f][nf][3] + by);
            *(float2*)cp = v0;
            *(float2*)(cp + (size_t)8 * H_) = v1;
        }
    }
}

// =================== Phase 2: tensor-core persistent scan ===================
// 64 persistent CTAs; CTA j owns output cols [j*16, j*16+16) with its Whh slice
// bf16-hi/lo in SMEM (tiled [kc][16][24]). h streams from global tiled bf16
// hi/lo via double-buffered cp.async stages of K=128. 8 warps = 4(m16) x 2(n8),
// full-K fragments -> no cross-warp reduction. 3-pass split MMA (hh+hl+lh).
#define SC_NCTA 64
#define SC_NC   16
#define SC_T    256
// smem (bytes): W hi 49152 | W lo 49152 | h stages 2 x (hi 24576 + lo 24576)
#define SC_WB    49152
#define SC_HSTG  24576                  // 8 kc-blocks x 64 rows x 24 elems x 2B
#define SC_HOFF  (2 * SC_WB)            // 98304
#define SC_SMEM  (SC_HOFF + 4 * SC_HSTG)  // 196608

__global__ __launch_bounds__(SC_T) void rnn_tc_kernel(
    const float* __restrict__ Whh,
    const float* __restrict__ Whh_b,
    float* __restrict__ y,      // [B,S,H], contains wx on entry
    float* __restrict__ hlast)  // [B,H] or nullptr
{
    extern __shared__ __nv_bfloat16 sm[];
    const uint32_t smb = smem_u32(sm);

    const int tid = threadIdx.x;
    const int wid = tid >> 5, lid = tid & 31;
    const int wm = wid >> 1, wn = wid & 1;        // 4(m) x 2(n)
    const int cta = blockIdx.x;
    const int g0 = cta * SC_NC;

    // ---- load + split this CTA's Whh slice into tiled smem (once) ----
    __nv_bfloat16* sWhi = sm;
    __nv_bfloat16* sWlo = sm + SC_WB / 2;
    for (int idx = tid; idx < SC_NC * H_; idx += SC_T) {
        int gr = idx >> 10, k = idx & 1023;
        float v = Whh[(size_t)(g0 + gr) * H_ + k];
        __nv_bfloat16 h = __float2bfloat16(v);
        __nv_bfloat16 l = __float2bfloat16(v - __bfloat162float(h));
        int si = ((k >> 4) * SC_NC + gr) * LDT + (k & 15);
        sWhi[si] = h; sWlo[si] = l;
    }
    __syncthreads();

    // ldmatrix lane offsets (same proven geometry as phase 1)
    const int grp = lid >> 3, li8 = lid & 7;
    const uint32_t offA  = (uint32_t)((wm * 16 + li8 + (grp & 1) * 8) * 48 + (grp >> 1) * 16);
    // B ldsm4 pairs two consecutive kc blocks (each block = 16 rows * 48 B = 768 B)
    const uint32_t offB4 = (uint32_t)((wn * 8 + li8) * 48 + (grp & 1) * 16 + (grp >> 1) * 768);

    // epilogue lane geometry
    const int b_r = wm * 16 + (lid >> 2);
    const int gc  = g0 + wn * 8 + (lid & 3) * 2;
    const float bi0 = Whh_b[gc], bi1 = Whh_b[gc + 1];

    for (int t = 0; t < S_; t++) {
        const __nv_bfloat16* hbhi = g_hb[t & 1][0];
        const __nv_bfloat16* hblo = g_hb[t & 1][1];
        __nv_bfloat16* hnhi = g_hb[(t & 1) ^ 1][0];
        __nv_bfloat16* hnlo = g_hb[(t & 1) ^ 1][1];

        // prefetch wx for this step (independent of h; latency hidden by k-loop)
        float2 wx0 = *(const float2*)&y[((size_t)b_r * S_ + t) * H_ + gc];
        float2 wx1 = *(const float2*)&y[((size_t)(b_r + 8) * S_ + t) * H_ + gc];

        auto issue = [&](int st, int buf) {
            #pragma unroll
            for (int i = 0; i < 8; i++) {
                int tt  = tid * 8 + i;            // 0..2047
                int hl  = tt >> 10;               // 0: hi, 1: lo
                int rem = tt & 1023;
                int kb  = rem >> 7;               // 0..7
                int b   = (rem >> 1) & 63;
                int s   = rem & 1;
                const __nv_bfloat16* src =
                    (hl ? hblo : hbhi) + ((size_t)(st * 8 + kb) * 64 + b) * 16 + s * 8;
                uint32_t dst = smb + SC_HOFF + (uint32_t)((buf * 2 + hl) * SC_HSTG
                               + ((kb * 64 + b) * LDT + s * 8) * 2);
                cp_async16(dst, src);
            }
            cp_commit();
        };

        issue(0, 0);
        issue(1, 1);

        float a0[4] = {0.f, 0.f, 0.f, 0.f};
        float a1[4] = {0.f, 0.f, 0.f, 0.f};
        float a2[4] = {0.f, 0.f, 0.f, 0.f};

        #pragma unroll 1
        for (int st = 0; st < 8; st++) {
            if (st == 7) cp_wait<0>(); else cp_wait<1>();
            __syncthreads();
            const uint32_t hshi = smb + SC_HOFF + (uint32_t)((st & 1) * 2 * SC_HSTG);
            const uint32_t hslo = hshi + SC_HSTG;
            #pragma unroll
            for (int kb = 0; kb < 8; kb += 2) {
                const int kc = st * 8 + kb;
                uint32_t B4h[4], B4l[4];
                ldsm4(B4h, smb + (uint32_t)(kc * 768) + offB4);
                ldsm4(B4l, smb + SC_WB + (uint32_t)(kc * 768) + offB4);
                #pragma unroll
                for (int j = 0; j < 2; j++) {
                    uint32_t Ah[4], Al[4];
                    ldsm4(Ah, hshi + (uint32_t)((kb + j) * 3072) + offA);
                    ldsm4(Al, hslo + (uint32_t)((kb + j) * 3072) + offA);
                    mma16816(a0, Ah, B4h + 2 * j);
                    mma16816(a1, Ah, B4l + 2 * j);
                    mma16816(a2, Al, B4h + 2 * j);
                }
            }
            __syncthreads();
            if (st + 2 < 8) issue(st + 2, st & 1);
        }

        // epilogue: tanh(wx + bias + sum), write y + split-bf16 h_next
        float v00 = tanhf(wx0.x + bi0 + (a0[0] + a1[0] + a2[0]));
        float v01 = tanhf(wx0.y + bi1 + (a0[1] + a1[1] + a2[1]));
        float v10 = tanhf(wx1.x + bi0 + (a0[2] + a1[2] + a2[2]));
        float v11 = tanhf(wx1.y + bi1 + (a0[3] + a1[3] + a2[3]));

        *(float2*)&y[((size_t)b_r * S_ + t) * H_ + gc]       = make_float2(v00, v01);
        *(float2*)&y[((size_t)(b_r + 8) * S_ + t) * H_ + gc] = make_float2(v10, v11);

        {
            __nv_bfloat16 h00 = __float2bfloat16(v00), h01 = __float2bfloat16(v01);
            __nv_bfloat16 h10 = __float2bfloat16(v10), h11 = __float2bfloat16(v11);
            __nv_bfloat16 l00 = __float2bfloat16(v00 - __bfloat162float(h00));
            __nv_bfloat16 l01 = __float2bfloat16(v01 - __bfloat162float(h01));
            __nv_bfloat16 l10 = __float2bfloat16(v10 - __bfloat162float(h10));
            __nv_bfloat16 l11 = __float2bfloat16(v11 - __bfloat162float(h11));
            int idx0 = (gc >> 4) * 1024 + b_r * 16 + (gc & 15);
            int idx1 = idx0 + 8 * 16;
            *(__nv_bfloat162*)&hnhi[idx0] = __halves2bfloat162(h00, h01);
            *(__nv_bfloat162*)&hnlo[idx0] = __halves2bfloat162(l00, l01);
            *(__nv_bfloat162*)&hnhi[idx1] = __halves2bfloat162(h10, h11);
            *(__nv_bfloat162*)&hnlo[idx1] = __halves2bfloat162(l10, l11);
        }

        if (hlast && t == S_ - 1) {
            *(float2*)&hlast[(size_t)b_r * H_ + gc]       = make_float2(v00, v01);
            *(float2*)&hlast[(size_t)(b_r + 8) * H_ + gc] = make_float2(v10, v11);
        }

        // grid barrier: monotone-target arrival counter
        __threadfence();
        __syncthreads();
        if (tid == 0) {
            atomicAdd(&g_bar, 1u);
            const unsigned target = (unsigned)(t + 1) * (unsigned)SC_NCTA;
            while (*((volatile unsigned*)&g_bar) < target) { __nanosleep(32); }
            __threadfence();
        }
        __syncthreads();
    }
}

// =================== launch ===================
extern "C" void kernel_launch(void* const* d_in, const int* in_sizes, int n_in,
                              void* d_out, int out_size) {
    (void)in_sizes; (void)n_in;
    const float* x     = (const float*)d_in[0];
    const float* h0    = (const float*)d_in[1];
    const float* Wih_w = (const float*)d_in[2];
    const float* Wih_b = (const float*)d_in[3];
    const float* Whh_w = (const float*)d_in[4];
    const float* Whh_b = (const float*)d_in[5];

    float* out   = (float*)d_out;
    float* y     = out;
    float* hlast = nullptr;
    const long long ybsh = (long long)B_ * S_ * H_;
    if ((long long)out_size >= ybsh + (long long)B_ * H_)
        hlast = out + ybsh;

    cudaFuncSetAttribute(rnn_tc_kernel, cudaFuncAttributeMaxDynamicSharedMemorySize,
                         SC_SMEM);

    // 1) init hidden state (tiled bf16 hi/lo) + barrier
    init_kernel<<<(B_ * H_ + 255) / 256, 256>>>(h0);

    // 2) bf16 hi/lo split of x and Wih
    convert_x_kernel<<<(B_ * S_ * I_ / 4) / 256, 256>>>(x);
    convert_w_kernel<<<(H_ * I_ / 4) / 256, 256>>>(Wih_w);

    // 3) wx = x @ Wih^T + b via mma.sync bf16 split (3 passes), into y
    dim3 gg(H_ / 128, (B_ * S_) / 128);
    gemm_wx_mma<<<gg, 256>>>(Wih_b, y);

    // 4) tensor-core persistent recurrent scan
    rnn_tc_kernel<<<SC_NCTA, SC_T, SC_SMEM>>>(Whh_w, Whh_b, y, hlast);
}

// round 10
// speedup vs baseline: 1.2159x; 1.2159x over previous
#include <cuda_runtime.h>
#include <cuda_bf16.h>
#include <math.h>
#include <stdint.h>

// Problem dims (fixed by the dataset)
#define B_  64
#define S_  1024
#define I_  1024
#define H_  1024

// =================== base-ISA PTX helpers (no sm_103a-only features) ===========
__device__ __forceinline__ uint32_t smem_u32(const void* p) {
    uint32_t a;
    asm("{ .reg .u64 t; cvta.to.shared.u64 t, %1; cvt.u32.u64 %0, t; }"
        : "=r"(a) : "l"(p));
    return a;
}
__device__ __forceinline__ void cp_async16(uint32_t saddr, const void* gaddr) {
    asm volatile("cp.async.cg.shared.global [%0], [%1], 16;"
                 :: "r"(saddr), "l"(gaddr));
}
__device__ __forceinline__ void cp_commit() {
    asm volatile("cp.async.commit_group;" ::: "memory");
}
template <int N>
__device__ __forceinline__ void cp_wait() {
    asm volatile("cp.async.wait_group %0;" :: "n"(N) : "memory");
}
__device__ __forceinline__ void ldsm4(uint32_t* r, uint32_t a) {
    asm volatile("ldmatrix.sync.aligned.m8n8.x4.shared.b16 {%0,%1,%2,%3}, [%4];"
                 : "=r"(r[0]), "=r"(r[1]), "=r"(r[2]), "=r"(r[3]) : "r"(a));
}
__device__ __forceinline__ void ldsm2(uint32_t* r, uint32_t a) {
    asm volatile("ldmatrix.sync.aligned.m8n8.x2.shared.b16 {%0,%1}, [%2];"
                 : "=r"(r[0]), "=r"(r[1]) : "r"(a));
}
// D(f32) += A(bf16) * B(bf16)^T, m16n8k16
__device__ __forceinline__ void mma16816(float* c, const uint32_t* a, const uint32_t* b) {
    asm volatile(
        "mma.sync.aligned.m16n8k16.row.col.f32.bf16.bf16.f32 "
        "{%0,%1,%2,%3}, {%4,%5,%6,%7}, {%8,%9}, {%0,%1,%2,%3};"
        : "+f"(c[0]), "+f"(c[1]), "+f"(c[2]), "+f"(c[3])
        : "r"(a[0]), "r"(a[1]), "r"(a[2]), "r"(a[3]), "r"(b[0]), "r"(b[1]));
}

// =================== persistent state (no allocations allowed) ===================
__device__ float    g_h[2][B_ * H_];   // ping-pong hidden state (fp32, R3-proven)
__device__ unsigned g_bar;             // grid barrier arrival counter
// bf16-split scratch for phase-1 tensor-core GEMM
__device__ __nv_bfloat16 g_xhi[(size_t)B_ * S_ * I_];
__device__ __nv_bfloat16 g_xlo[(size_t)B_ * S_ * I_];
__device__ __nv_bfloat16 g_whi[(size_t)H_ * I_];
__device__ __nv_bfloat16 g_wlo[(size_t)H_ * I_];

// =================== init: copy h0, reset barrier ===================
__global__ void init_kernel(const float* __restrict__ h0) {
    int i = blockIdx.x * blockDim.x + threadIdx.x;
    if (i < B_ * H_) g_h[0][i] = h0[i];
    if (i == 0) g_bar = 0u;
}

// =================== fp32 -> (hi, lo) bf16 split (x, Wih) ===================
__global__ void convert_x_kernel(const float* __restrict__ src) {
    size_t i = (size_t)blockIdx.x * blockDim.x + threadIdx.x;   // one float4
    float4 v = ((const float4*)src)[i];
    __nv_bfloat16 hx = __float2bfloat16(v.x), hy = __float2bfloat16(v.y);
    __nv_bfloat16 hz = __float2bfloat16(v.z), hw = __float2bfloat16(v.w);
    __nv_bfloat16 lx = __float2bfloat16(v.x - __bfloat162float(hx));
    __nv_bfloat16 ly = __float2bfloat16(v.y - __bfloat162float(hy));
    __nv_bfloat16 lz = __float2bfloat16(v.z - __bfloat162float(hz));
    __nv_bfloat16 lw = __float2bfloat16(v.w - __bfloat162float(hw));
    __nv_bfloat162* dh = ((__nv_bfloat162*)g_xhi) + 2 * i;
    __nv_bfloat162* dl = ((__nv_bfloat162*)g_xlo) + 2 * i;
    dh[0] = __halves2bfloat162(hx, hy); dh[1] = __halves2bfloat162(hz, hw);
    dl[0] = __halves2bfloat162(lx, ly); dl[1] = __halves2bfloat162(lz, lw);
}
__global__ void convert_w_kernel(const float* __restrict__ src) {
    size_t i = (size_t)blockIdx.x * blockDim.x + threadIdx.x;
    float4 v = ((const float4*)src)[i];
    __nv_bfloat16 hx = __float2bfloat16(v.x), hy = __float2bfloat16(v.y);
    __nv_bfloat16 hz = __float2bfloat16(v.z), hw = __float2bfloat16(v.w);
    __nv_bfloat16 lx = __float2bfloat16(v.x - __bfloat162float(hx));
    __nv_bfloat16 ly = __float2bfloat16(v.y - __bfloat162float(hy));
    __nv_bfloat16 lz = __float2bfloat16(v.z - __bfloat162float(hz));
    __nv_bfloat16 lw = __float2bfloat16(v.w - __bfloat162float(hw));
    __nv_bfloat162* dh = ((__nv_bfloat162*)g_whi) + 2 * i;
    __nv_bfloat162* dl = ((__nv_bfloat162*)g_wlo) + 2 * i;
    dh[0] = __halves2bfloat162(hx, hy); dh[1] = __halves2bfloat162(hz, hw);
    dl[0] = __halves2bfloat162(lx, ly); dl[1] = __halves2bfloat162(lz, lw);
}

// =================== Phase 1: mma.sync bf16-split GEMM (proven R8) ==============
#define BKE   16
#define LDT   24
#define TILE_E (128 * LDT)          // 3072 elems = 6144 B
#define NKC   (I_ / BKE)            // 64

__global__ __launch_bounds__(256) void gemm_wx_mma(const float* __restrict__ bias,
                                                   float* __restrict__ C) {
    __shared__ __nv_bfloat16 stg[2][4][TILE_E];   // 49152 B

    const int tid = threadIdx.x;
    const int wid = tid >> 5, lid = tid & 31;
    const int wm = wid >> 2, wn = wid & 3;        // 2 x 4 warps
    const int m0 = blockIdx.y * 128, n0 = blockIdx.x * 128;
    const uint32_t sb = smem_u32(stg);

    const int ltile = tid >> 6;                   // 0..3
    const int lrow2 = (tid & 63) * 2;

    const int grp = lid >> 3, li8 = lid & 7;
    uint32_t offA[4], offB[4];
    #pragma unroll
    for (int f = 0; f < 4; f++)
        offA[f] = (uint32_t)((wm * 64 + f * 16 + li8 + (grp & 1) * 8) * 48 + (grp >> 1) * 16);
    #pragma unroll
    for (int nf = 0; nf < 4; nf++)
        offB[nf] = (uint32_t)((wn * 32 + nf * 8 + li8) * 48 + (grp & 1) * 16);

    float acc[4][4][4];
    #pragma unroll
    for (int f = 0; f < 4; f++)
        #pragma unroll
        for (int nf = 0; nf < 4; nf++)
            #pragma unroll
            for (int q = 0; q < 4; q++) acc[f][nf][q] = 0.f;

    auto load_stage = [&](int kc, int s) {
        const int koff = kc * BKE;
        #pragma unroll
        for (int i = 0; i < 4; i++) {
            const int row = lrow2 + (i >> 1), seg = i & 1;
            const __nv_bfloat16* gp;
            if      (ltile == 0) gp = g_xhi + (size_t)(m0 + row) * I_ + koff + seg * 8;
            else if (ltile == 1) gp = g_xlo + (size_t)(m0 + row) * I_ + koff + seg * 8;
            else if (ltile == 2) gp = g_whi + (size_t)(n0 + row) * I_ + koff + seg * 8;
            else                 gp = g_wlo + (size_t)(n0 + row) * I_ + koff + seg * 8;
            uint32_t sa = sb + (uint32_t)(((s * 4 + ltile) * TILE_E + row * LDT + seg * 8) * 2);
            cp_async16(sa, gp);
        }
        cp_commit();
    };

    load_stage(0, 0);

    for (int kc = 0; kc < NKC; kc++) {
        const int s = kc & 1;
        if (kc + 1 < NKC) { load_stage(kc + 1, s ^ 1); cp_wait<1>(); }
        else             { cp_wait<0>(); }
        __syncthreads();

        const uint32_t base = sb + (uint32_t)(s * 4 * TILE_E * 2);
        const uint32_t tAh = base, tAl = base + 6144, tBh = base + 12288, tBl = base + 18432;

        uint32_t Ah[4][4], Al[4][4], Bh[4][2], Bl[4][2];
        #pragma unroll
        for (int f = 0; f < 4; f++) { ldsm4(Ah[f], tAh + offA[f]); ldsm4(Al[f], tAl + offA[f]); }
        #pragma unroll
        for (int nf = 0; nf < 4; nf++) { ldsm2(Bh[nf], tBh + offB[nf]); ldsm2(Bl[nf], tBl + offB[nf]); }

        #pragma unroll
        for (int f = 0; f < 4; f++)
            #pragma unroll
            for (int nf = 0; nf < 4; nf++) {
                mma16816(acc[f][nf], Ah[f], Bh[nf]);
                mma16816(acc[f][nf], Ah[f], Bl[nf]);
                mma16816(acc[f][nf], Al[f], Bh[nf]);
            }
        __syncthreads();
    }

    #pragma unroll
    for (int nf = 0; nf < 4; nf++) {
        const int col = n0 + wn * 32 + nf * 8 + (lid & 3) * 2;
        const float bx = bias[col], by = bias[col + 1];
        #pragma unroll
        for (int f = 0; f < 4; f++) {
            const size_t r0 = (size_t)(m0 + wm * 64 + f * 16 + (lid >> 2));
            float* cp = C + r0 * H_ + col;
            float2 v0 = make_float2(acc[f][nf][0] + bx, acc[f][nf][1] + by);
            float2 v1 = make_float2(acc[f][nf][2] + bx, acc[f][nf][3] + by);
            *(float2*)cp = v0;
            *(float2*)(cp + (size_t)8 * H_) = v1;
        }
    }
}

// =================== Phase 2: persistent recurrent scan (proven R3) =============
// 128 resident CTAs; CTA j owns output columns [j*8, j*8+8) with its Whh slice
// resident in SMEM. 4-batch x 4-col x 8-way-K-split register tile, scalar FFMA.
#define NCTA   128
#define CPC    8            // output columns per CTA
#define T2     256          // threads per CTA
#define HCH    64           // h K-chunk staged in smem
#define NCHUNK (H_ / HCH)   // 16

__global__ __launch_bounds__(T2) void rnn_steps_kernel(
    const float* __restrict__ Whh,
    const float* __restrict__ Whh_b,
    float* __restrict__ y,      // [B,S,H], contains wx on entry
    float* __restrict__ hlast)  // [B,H] or nullptr
{
    __shared__ __align__(16) float sW[CPC * H_];  // 32 KB: Whh slice, [c][k] (contig)
    __shared__ __align__(16) float sh[B_ * HCH];  // 16 KB: h chunk [b][k]; reused as stage

    const int cta = blockIdx.x;
    const int tid = threadIdx.x;
    const int g0  = cta * CPC;

    // Load this CTA's Whh slice once (rows g0..g0+7 are contiguous in global).
    for (int v = tid; v < CPC * H_; v += T2)
        sW[v] = Whh[(size_t)g0 * H_ + v];

    // Thread decomposition: ks = K-split lane (8-way), cg = col group (2), bg = batch group (16)
    const int ks = tid & 7;
    const int cg = (tid >> 3) & 1;
    const int bg = tid >> 4;
    const int b0 = bg << 2;   // 4 batches per thread
    const int c0 = cg << 2;   // 4 cols per thread

    const float bi_fin = Whh_b[g0 + (tid & 7)];  // bias for finalize lane (gl = tid&7)

    for (int t = 0; t < S_; t++) {
        const float* hc = g_h[t & 1];
        float*       hn = g_h[(t & 1) ^ 1];

        // Prefetch chunk 0 of h into registers (post-barrier, data is final).
        float4 pf[4];
        #pragma unroll
        for (int i = 0; i < 4; i++) {
            int v = tid + i * T2;          // 0..1023 float4s = 64x64 floats
            int b  = v >> 4;
            int kl = (v & 15) << 2;
            pf[i] = *(const float4*)&hc[(size_t)b * H_ + kl];
        }

        float acc[4][4];
        #pragma unroll
        for (int j = 0; j < 4; j++)
            #pragma unroll
            for (int c = 0; c < 4; c++) acc[j][c] = 0.f;

        #pragma unroll 1
        for (int kc = 0; kc < NCHUNK; kc++) {
            __syncthreads();               // sh free for overwrite
            #pragma unroll
            for (int i = 0; i < 4; i++) {
                int v = tid + i * T2;
                int b  = v >> 4;
                int kl = (v & 15) << 2;
                *(float4*)&sh[b * HCH + kl] = pf[i];
            }
            if (kc + 1 < NCHUNK) {         // prefetch next chunk, hidden under compute
                #pragma unroll
                for (int i = 0; i < 4; i++) {
                    int v = tid + i * T2;
                    int b  = v >> 4;
                    int kl = (v & 15) << 2;
                    pf[i] = *(const float4*)&hc[(size_t)b * H_ + (kc + 1) * HCH + kl];
                }
            }
            __syncthreads();
            const int kgb = kc * HCH;
            #pragma unroll
            for (int i = 0; i < 2; i++) {
                // interleaved K-split: lane ks takes k = i*32 + ks*4 .. +3
                const int klo = (i << 5) + (ks << 2);
                float4 hv[4], wv[4];
                #pragma unroll
                for (int j = 0; j < 4; j++)
                    hv[j] = *(const float4*)&sh[(b0 + j) * HCH + klo];
                #pragma unroll
                for (int c = 0; c < 4; c++)
                    wv[c] = *(const float4*)&sW[(c0 + c) * H_ + kgb + klo];
                #pragma unroll
                for (int j = 0; j < 4; j++)
                    #pragma unroll
                    for (int c = 0; c < 4; c++) {
                        acc[j][c] += hv[j].x * wv[c].x;
                        acc[j][c] += hv[j].y * wv[c].y;
                        acc[j][c] += hv[j].z * wv[c].z;
                        acc[j][c] += hv[j].w * wv[c].w;
                    }
            }
        }

        // Reduce the 8-way K-split: ks lanes are adjacent -> butterfly within 8-lane groups.
        #pragma unroll
        for (int j = 0; j < 4; j++)
            #pragma unroll
            for (int c = 0; c < 4; c++) {
                float v = acc[j][c];
                v += __shfl_xor_sync(0xFFFFFFFFu, v, 1);
                v += __shfl_xor_sync(0xFFFFFFFFu, v, 2);
                v += __shfl_xor_sync(0xFFFFFFFFu, v, 4);
                acc[j][c] = v;
            }

        __syncthreads();                    // done reading sh (chunk data)
        // Stage 512 sums into sh for coalesced finalize (2 values per thread).
        #pragma unroll
        for (int q = 0; q < 2; q++) {
            int p = (ks << 1) + q;          // 0..15 within the (bg,cg) group
            int j = p >> 2, c = p & 3;
            sh[(b0 + j) * CPC + (c0 + c)] = acc[j][c];
        }
        __syncthreads();

        // Finalize: read wx in place, tanh, write y / h_next (/ h_last).
        #pragma unroll
        for (int q = 0; q < 2; q++) {
            int o  = tid + q * T2;          // 0..511
            int b  = o >> 3;
            int gl = o & 7;                 // == tid&7 for both q -> bi_fin valid
            size_t yi = ((size_t)b * S_ + t) * H_ + g0 + gl;
            float val = tanhf(y[yi] + bi_fin + sh[o]);
            y[yi] = val;
            hn[(size_t)b * H_ + g0 + gl] = val;
            if (hlast && t == S_ - 1) hlast[(size_t)b * H_ + g0 + gl] = val;
        }

        // Grid barrier: monotone-target arrival counter (reset by init_kernel).
        __threadfence();
        __syncthreads();
        if (tid == 0) {
            atomicAdd(&g_bar, 1u);
            const unsigned target = (unsigned)(t + 1) * (unsigned)NCTA;
            while (*((volatile unsigned*)&g_bar) < target) { __nanosleep(64); }
            __threadfence();
        }
        __syncthreads();
    }
}

// =================== launch ===================
extern "C" void kernel_launch(void* const* d_in, const int* in_sizes, int n_in,
                              void* d_out, int out_size) {
    (void)in_sizes; (void)n_in;
    const float* x     = (const float*)d_in[0];
    const float* h0    = (const float*)d_in[1];
    const float* Wih_w = (const float*)d_in[2];
    const float* Wih_b = (const float*)d_in[3];
    const float* Whh_w = (const float*)d_in[4];
    const float* Whh_b = (const float*)d_in[5];

    float* out   = (float*)d_out;
    float* y     = out;                              // [B,S,H]
    float* hlast = nullptr;                          // [B,H] appended if present
    const long long ybsh = (long long)B_ * S_ * H_;
    if ((long long)out_size >= ybsh + (long long)B_ * H_)
        hlast = out + ybsh;

    // 1) init hidden state + barrier
    init_kernel<<<(B_ * H_ + 255) / 256, 256>>>(h0);

    // 2) bf16 hi/lo split of x and Wih
    convert_x_kernel<<<(B_ * S_ * I_ / 4) / 256, 256>>>(x);
    convert_w_kernel<<<(H_ * I_ / 4) / 256, 256>>>(Wih_w);

    // 3) wx = x @ Wih^T + b via mma.sync bf16 split (3 passes), into y
    dim3 gg(H_ / 128, (B_ * S_) / 128);   // x-fastest: N-tiles share A panel in L2
    gemm_wx_mma<<<gg, 256>>>(Wih_b, y);

    // 4) persistent recurrent scan (128 resident CTAs, internal grid barrier)
    rnn_steps_kernel<<<NCTA, T2>>>(Whh_w, Whh_b, y, hlast);
}